// round 15
// baseline (speedup 1.0000x reference)
#include <cuda_runtime.h>
#include <cuda_bf16.h>
#include <cuda_fp16.h>
#include <mma.h>

using namespace nvcuda;

constexpr int B_   = 8;
constexpr int H_   = 8;
constexpr int S_   = 1024;
constexpr int DK_  = 64;
constexpr int EMB_ = 512;
constexpr int HD_  = 512;   // H*DK
constexpr int BH_  = 64;    // B*H
constexpr int SD_  = S_ * DK_;   // 65536
constexpr int SS_  = S_ * S_;    // 1048576
constexpr int THP  = 1032;       // sT row stride in halfs (2064B: 16B-aligned rows)

// Scratch (device globals: allocation-free rule)
__device__ __half gQh[BH_ * S_ * DK_];  // fp16, q pre-scaled by 1/8
__device__ __half gKh[BH_ * S_ * DK_];
__device__ __half gVh[BH_ * S_ * DK_];
__device__ float  gO[BH_ * S_ * DK_];
// gS (fp16, 128MB): score-bias before softmax; attention weights after softmax
__device__ __half gS[(size_t)BH_ * S_ * S_];

// ---------------------------------------------------------------------------
// Kernel 1: merged QKV projection, single fp16 MMA. Tile 128x64, k-chunk 64.
// Register-prefetch pipelined.
// ---------------------------------------------------------------------------
__global__ __launch_bounds__(256, 2)
void proj_kernel(const float* __restrict__ Xq, const float* __restrict__ Xk,
                 const float* __restrict__ Xv,
                 const float* __restrict__ Wq, const float* __restrict__ Wk,
                 const float* __restrict__ Wv,
                 const float* __restrict__ bq, const float* __restrict__ bk,
                 const float* __restrict__ bv)
{
    extern __shared__ char psm[];
    __half* sA = (__half*)psm;               // 128 x 72
    __half* sB = sA + 128 * 72;              // 64 x 72
    float* sBias = (float*)(sB + 64 * 72);   // 16 x 72
    float* stage = (float*)psm;              // epilogue reuse: 128 x 68

    const int which = blockIdx.z;
    const float* X    = (which == 0) ? Xq : (which == 1) ? Xk : Xv;
    const float* W    = (which == 0) ? Wq : (which == 1) ? Wk : Wv;
    const float* bias = (which == 0) ? bq : (which == 1) ? bk : bv;
    __half* outp      = (which == 0) ? gQh : (which == 1) ? gKh : gVh;
    const float scale = (which == 0) ? 0.125f : 1.0f;

    const int tid = threadIdx.x;
    const int wid = tid >> 5;
    const int warpRow = wid >> 1;   // 0..3
    const int warpCol = wid & 1;    // 0..1
    const int m0 = blockIdx.y * 128;
    const int n0 = blockIdx.x * 64;
    const int bb = m0 >> 10;
    const int sBase = m0 & 1023;
    const int h  = n0 >> 6;
    const int rowA = tid >> 4;      // 0..15
    const int c4   = (tid & 15) * 4;

    #pragma unroll
    for (int i = 0; i < 4; i++) {
        int idx = tid + i * 256;
        int r = idx >> 6, c = idx & 63;
        sBias[r * 72 + c] = bias[n0 + c];
    }
    __syncthreads();

    wmma::fragment<wmma::accumulator, 16, 16, 16, float> acc[2][2];
    #pragma unroll
    for (int mi = 0; mi < 2; mi++)
        #pragma unroll
        for (int ni = 0; ni < 2; ni++)
            wmma::load_matrix_sync(acc[mi][ni], sBias + warpCol * 32 + ni * 16,
                                   72, wmma::mem_row_major);

    // prefetch chunk 0
    float4 pA[8], pW[4];
    #pragma unroll
    for (int i = 0; i < 8; i++)
        pA[i] = *(const float4*)(X + (m0 + rowA + i * 16) * EMB_ + c4);
    #pragma unroll
    for (int i = 0; i < 4; i++)
        pW[i] = *(const float4*)(W + (rowA + i * 16) * HD_ + n0 + c4);

    for (int kt = 0; kt < 8; kt++) {
        __syncthreads();
        #pragma unroll
        for (int i = 0; i < 8; i++) {
            int row = rowA + i * 16;
            *(__half2*)&sA[row * 72 + c4]     = __floats2half2_rn(pA[i].x, pA[i].y);
            *(__half2*)&sA[row * 72 + c4 + 2] = __floats2half2_rn(pA[i].z, pA[i].w);
        }
        #pragma unroll
        for (int i = 0; i < 4; i++) {
            int row = rowA + i * 16;
            *(__half2*)&sB[row * 72 + c4]     = __floats2half2_rn(pW[i].x, pW[i].y);
            *(__half2*)&sB[row * 72 + c4 + 2] = __floats2half2_rn(pW[i].z, pW[i].w);
        }
        __syncthreads();
        if (kt < 7) {
            const int k1 = (kt + 1) * 64;
            #pragma unroll
            for (int i = 0; i < 8; i++)
                pA[i] = *(const float4*)(X + (m0 + rowA + i * 16) * EMB_ + k1 + c4);
            #pragma unroll
            for (int i = 0; i < 4; i++)
                pW[i] = *(const float4*)(W + (k1 + rowA + i * 16) * HD_ + n0 + c4);
        }
        #pragma unroll
        for (int kk = 0; kk < 4; kk++) {
            wmma::fragment<wmma::matrix_b, 16, 16, 16, __half, wmma::row_major> bf[2];
            #pragma unroll
            for (int ni = 0; ni < 2; ni++)
                wmma::load_matrix_sync(bf[ni], sB + (kk * 16) * 72 + warpCol * 32 + ni * 16, 72);
            #pragma unroll
            for (int mi = 0; mi < 2; mi++) {
                wmma::fragment<wmma::matrix_a, 16, 16, 16, __half, wmma::row_major> a;
                wmma::load_matrix_sync(a, sA + (warpRow * 32 + mi * 16) * 72 + kk * 16, 72);
                #pragma unroll
                for (int ni = 0; ni < 2; ni++)
                    wmma::mma_sync(acc[mi][ni], a, bf[ni], acc[mi][ni]);
            }
        }
    }
    __syncthreads();

    // Epilogue: scale, stage fp32, write fp16
    #pragma unroll
    for (int mi = 0; mi < 2; mi++)
        #pragma unroll
        for (int ni = 0; ni < 2; ni++) {
            #pragma unroll
            for (int e = 0; e < acc[mi][ni].num_elements; e++)
                acc[mi][ni].x[e] *= scale;
            wmma::store_matrix_sync(stage + (warpRow * 32 + mi * 16) * 68 + warpCol * 32 + ni * 16,
                                    acc[mi][ni], 68, wmma::mem_row_major);
        }
    __syncthreads();
    __half* obase = outp + ((size_t)((bb * H_ + h) << 16));
    #pragma unroll
    for (int i = 0; i < 16; i++) {
        int idx = tid + i * 256;
        int r = idx >> 5, cp = (idx & 31) * 2;
        float2 v = *(float2*)(stage + r * 68 + cp);
        *(__half2*)(obase + (size_t)(sBase + r) * DK_ + cp) = __floats2half2_rn(v.x, v.y);
    }
}

// ---------------------------------------------------------------------------
// Kernel 2: gS[bh,q,n] = gQh[bh,q,:]·Ek[q,n,:] + abias[b,q,n]. fp16 MMA.
// acc=0; abias added in epilogue from global (coalesced); fp16 out to gS.
// ---------------------------------------------------------------------------
__global__ __launch_bounds__(256, 4)
void edge_bias_kernel(const float* __restrict__ Ek, const float* __restrict__ abias)
{
    extern __shared__ char esm[];
    __half* sA  = (__half*)esm;              // 64 x 72 (row=bh, col=d)
    __half* sEk = sA + 64 * 72;              // 64 x 72 (row=n, col=d)
    float* stg  = (float*)(sEk + 64 * 72);   // 64 x 72 fp32 stage

    const int tid = threadIdx.x;
    const int wid = tid >> 5;
    const int wr  = wid >> 2;            // 0..1
    const int wc  = wid & 3;             // 0..3 -> 16 cols
    const int q   = blockIdx.y;
    const int n0  = blockIdx.x * 64;
    const int rowA = tid >> 4;           // 0..15
    const int c4   = (tid & 15) * 4;

    #pragma unroll
    for (int i = 0; i < 4; i++) {
        int row = rowA + i * 16;
        *(uint2*)&sA[row * 72 + c4] =
            *(const uint2*)(gQh + (size_t)row * SD_ + q * DK_ + c4);
        float4 v = *(const float4*)(Ek + ((size_t)q * S_ + n0 + row) * DK_ + c4);
        *(__half2*)&sEk[row * 72 + c4]     = __floats2half2_rn(v.x, v.y);
        *(__half2*)&sEk[row * 72 + c4 + 2] = __floats2half2_rn(v.z, v.w);
    }
    __syncthreads();

    wmma::fragment<wmma::accumulator, 16, 16, 16, float> acc[2];
    wmma::fill_fragment(acc[0], 0.0f);
    wmma::fill_fragment(acc[1], 0.0f);

    #pragma unroll
    for (int kk = 0; kk < 4; kk++) {
        wmma::fragment<wmma::matrix_b, 16, 16, 16, __half, wmma::col_major> b;
        wmma::load_matrix_sync(b, sEk + (wc * 16) * 72 + kk * 16, 72);
        #pragma unroll
        for (int mi = 0; mi < 2; mi++) {
            wmma::fragment<wmma::matrix_a, 16, 16, 16, __half, wmma::row_major> a;
            wmma::load_matrix_sync(a, sA + (wr * 32 + mi * 16) * 72 + kk * 16, 72);
            wmma::mma_sync(acc[mi], a, b, acc[mi]);
        }
    }

    #pragma unroll
    for (int mi = 0; mi < 2; mi++)
        wmma::store_matrix_sync(stg + (wr * 32 + mi * 16) * 72 + wc * 16,
                                acc[mi], 72, wmma::mem_row_major);
    __syncthreads();
    #pragma unroll
    for (int i = 0; i < 8; i++) {
        int idx = tid + i * 256;
        int r = idx >> 5, u = idx & 31;
        float2 f = *(float2*)(stg + r * 72 + 2 * u);
        float2 ab = *(const float2*)(abias + (size_t)(r >> 3) * SS_ + (size_t)q * S_ + n0 + 2 * u);
        ((__half2*)(gS + (size_t)r * SS_ + (size_t)q * S_ + n0))[u] =
            __floats2half2_rn(f.x + ab.x, f.y + ab.y);
    }
}

// ---------------------------------------------------------------------------
// Kernel 3 (FUSED): 16 q-rows/CTA, 4 CTAs/SM. fp16 QK^T (fp16 acc) -> fp16
// scores in sT -> 3-pass softmax -> fp16 weights in sT + gS -> fp16 W @ V
// with double-buffered 64-row V chunks (1 sync/chunk).
// ---------------------------------------------------------------------------
__global__ __launch_bounds__(256, 4)
void fused_attn_kernel()
{
    extern __shared__ char fsm[];
    __half* sQ  = (__half*)fsm;              // 16 x 72
    __half* sKV = sQ + 16 * 72;              // 128 x 72 (phase A) / 2 x (64 x 72) (phase C)
    __half* sT  = sKV + 128 * 72;            // 16 x THP (fp16 scores/weights)

    const int tid = threadIdx.x;
    const int wid = tid >> 5;
    const int lane = tid & 31;
    const int bh = blockIdx.y;
    const int q0 = blockIdx.x * 16;
    const int rowA = tid >> 4;               // 0..15
    const int c4   = (tid & 15) * 4;         // half-index

    {
        int row = tid >> 4, cc = (tid & 15) * 4;
        *(uint2*)&sQ[row * 72 + cc] =
            *(const uint2*)(gQh + (size_t)bh * SD_ + (q0 + row) * DK_ + cc);
    }
    __syncthreads();

    // ---- Phase A: raw scores, fp16 MMA with fp16 accumulator ----
    {
        wmma::fragment<wmma::matrix_a, 16, 16, 16, __half, wmma::row_major> a[4];
        #pragma unroll
        for (int kk = 0; kk < 4; kk++)
            wmma::load_matrix_sync(a[kk], sQ + kk * 16, 72);

        const __half* Kbase = gKh + (size_t)bh * SD_;
        uint2 pK[8];
        #pragma unroll
        for (int i = 0; i < 8; i++)
            pK[i] = *(const uint2*)(Kbase + (rowA + i * 16) * DK_ + c4);

        for (int nc = 0; nc < 8; nc++) {
            __syncthreads();
            #pragma unroll
            for (int i = 0; i < 8; i++)
                *(uint2*)&sKV[(rowA + i * 16) * 72 + c4] = pK[i];
            __syncthreads();
            if (nc < 7) {
                const int n1 = (nc + 1) * 128;
                #pragma unroll
                for (int i = 0; i < 8; i++)
                    pK[i] = *(const uint2*)(Kbase + (n1 + rowA + i * 16) * DK_ + c4);
            }
            const int ncol = wid * 16;
            wmma::fragment<wmma::accumulator, 16, 16, 16, __half> acc;
            wmma::fill_fragment(acc, __float2half(0.0f));
            #pragma unroll
            for (int kk = 0; kk < 4; kk++) {
                wmma::fragment<wmma::matrix_b, 16, 16, 16, __half, wmma::col_major> b;
                wmma::load_matrix_sync(b, sKV + ncol * 72 + kk * 16, 72);
                wmma::mma_sync(acc, a[kk], b, acc);
            }
            wmma::store_matrix_sync(sT + nc * 128 + ncol, acc, THP, wmma::mem_row_major);
        }
    }
    __syncthreads();

    // ---- Phase B: 3-pass softmax over fp16 scores + fp16 bias ----
    #pragma unroll
    for (int rr = 0; rr < 2; rr++) {
        int r = wid * 2 + rr;
        __half2* row2 = (__half2*)(sT + r * THP);
        __half2* gb = (__half2*)(gS + ((size_t)bh * S_ + q0 + r) * S_);
        float mx = -3.0e38f;
        #pragma unroll
        for (int jj = 0; jj < 16; jj++) {
            int p = lane + 32 * jj;
            float2 s = __half22float2(row2[p]);
            float2 bv = __half22float2(gb[p]);
            mx = fmaxf(mx, fmaxf(s.x + bv.x, s.y + bv.y));
        }
        #pragma unroll
        for (int o = 16; o; o >>= 1) mx = fmaxf(mx, __shfl_xor_sync(0xffffffffu, mx, o));
        float sum = 0.0f;
        #pragma unroll
        for (int jj = 0; jj < 16; jj++) {
            int p = lane + 32 * jj;
            float2 s = __half22float2(row2[p]);
            float2 bv = __half22float2(gb[p]);
            float e0 = expf(s.x + bv.x - mx);
            float e1 = expf(s.y + bv.y - mx);
            row2[p] = __floats2half2_rn(e0, e1);
            sum += e0 + e1;
        }
        #pragma unroll
        for (int o = 16; o; o >>= 1) sum += __shfl_xor_sync(0xffffffffu, sum, o);
        float inv = 1.0f / sum;
        #pragma unroll
        for (int jj = 0; jj < 16; jj++) {
            int p = lane + 32 * jj;
            float2 e = __half22float2(row2[p]);
            __half2 w = __floats2half2_rn(e.x * inv, e.y * inv);
            row2[p] = w;
            gb[p] = w;
        }
    }
    __syncthreads();

    // ---- Phase C: out = weights @ V; 64-row chunks, double-buffered sKV,
    //      ONE sync per chunk; kk split across warp halves ----
    {
        const int kg = wid >> 2;   // 0..1: kk {0,1} vs {2,3}
        const int wc = wid & 3;    // 0..3 -> 16 cols
        wmma::fragment<wmma::accumulator, 16, 16, 16, float> c[2];
        wmma::fill_fragment(c[0], 0.0f);
        wmma::fill_fragment(c[1], 0.0f);
        const __half* Vbase = gVh + (size_t)bh * SD_;

        uint2 pV[4];
        #pragma unroll
        for (int i = 0; i < 4; i++)
            pV[i] = *(const uint2*)(Vbase + (rowA + i * 16) * DK_ + c4);

        for (int kt = 0; kt < 16; kt++) {
            __half* buf = sKV + (kt & 1) * (64 * 72);
            #pragma unroll
            for (int i = 0; i < 4; i++)
                *(uint2*)&buf[(rowA + i * 16) * 72 + c4] = pV[i];
            __syncthreads();
            if (kt < 15) {
                const int k1 = (kt + 1) * 64;
                #pragma unroll
                for (int i = 0; i < 4; i++)
                    pV[i] = *(const uint2*)(Vbase + (k1 + rowA + i * 16) * DK_ + c4);
            }
            #pragma unroll
            for (int kx = 0; kx < 2; kx++) {
                const int kk = kg * 2 + kx;
                wmma::fragment<wmma::matrix_a, 16, 16, 16, __half, wmma::row_major> a;
                wmma::fragment<wmma::matrix_b, 16, 16, 16, __half, wmma::row_major> b;
                wmma::load_matrix_sync(a, sT + kt * 64 + kk * 16, THP);
                wmma::load_matrix_sync(b, buf + (kk * 16) * 72 + wc * 16, 72);
                wmma::mma_sync(c[kx], a, b, c[kx]);
            }
        }
        #pragma unroll
        for (int e = 0; e < c[0].num_elements; e++) c[0].x[e] += c[1].x[e];

        // all warps must finish reading sT (weights) before recycling it
        __syncthreads();

        float* red = (float*)sT;   // weights dead; reuse as 16x68 fp32 stage
        if (kg == 1)
            wmma::store_matrix_sync(red + wc * 16, c[0], 68, wmma::mem_row_major);
        __syncthreads();
        if (kg == 0) {
            wmma::fragment<wmma::accumulator, 16, 16, 16, float> t;
            wmma::load_matrix_sync(t, red + wc * 16, 68, wmma::mem_row_major);
            #pragma unroll
            for (int e = 0; e < c[0].num_elements; e++) c[0].x[e] += t.x[e];
            wmma::store_matrix_sync(gO + (size_t)bh * SD_ + (size_t)q0 * DK_ + wc * 16,
                                    c[0], DK_, wmma::mem_row_major);
        }
    }
}

// ---------------------------------------------------------------------------
// Kernel 4: gO += weights[:,q,:] @ Ev[q].  fp16 MMA, fp16 weights from gS.
// ---------------------------------------------------------------------------
__global__ __launch_bounds__(256, 4)
void edgev_kernel(const float* __restrict__ Ev)
{
    __shared__ __half sA[64 * 72];
    __shared__ __half sB[64 * 72];

    const int tid = threadIdx.x;
    const int wid = tid >> 5;
    const int warpRow = wid >> 1;   // 0..3
    const int warpCol = wid & 1;    // 0..1
    const int q = blockIdx.x;
    const int rowA = tid >> 4;      // 0..15
    const int c4   = (tid & 15) * 4;

    wmma::fragment<wmma::accumulator, 16, 16, 16, float> acc[2];
    #pragma unroll
    for (int j = 0; j < 2; j++)
        wmma::load_matrix_sync(acc[j],
            gO + (size_t)(warpRow * 16) * SD_ + q * DK_ + warpCol * 32 + j * 16,
            SD_, wmma::mem_row_major);

    uint2  pA[4];
    float4 pB[4];
    #pragma unroll
    for (int i = 0; i < 4; i++) {
        int row = rowA + i * 16;
        pA[i] = *(const uint2*)(gS + (size_t)row * SS_ + (size_t)q * S_ + c4);
        pB[i] = *(const float4*)(Ev + ((size_t)q * S_ + row) * DK_ + c4);
    }

    for (int kt = 0; kt < 16; kt++) {
        __syncthreads();
        #pragma unroll
        for (int i = 0; i < 4; i++) {
            int row = rowA + i * 16;
            *(uint2*)&sA[row * 72 + c4] = pA[i];
            float4 v = pB[i];
            *(__half2*)&sB[row * 72 + c4]     = __floats2half2_rn(v.x, v.y);
            *(__half2*)&sB[row * 72 + c4 + 2] = __floats2half2_rn(v.z, v.w);
        }
        __syncthreads();
        if (kt < 15) {
            const int k1 = (kt + 1) * 64;
            #pragma unroll
            for (int i = 0; i < 4; i++) {
                int row = rowA + i * 16;
                pA[i] = *(const uint2*)(gS + (size_t)row * SS_ + (size_t)q * S_ + k1 + c4);
                pB[i] = *(const float4*)(Ev + ((size_t)q * S_ + k1 + row) * DK_ + c4);
            }
        }
        #pragma unroll
        for (int kk = 0; kk < 4; kk++) {
            wmma::fragment<wmma::matrix_a, 16, 16, 16, __half, wmma::row_major> a;
            wmma::load_matrix_sync(a, sA + (warpRow * 16) * 72 + kk * 16, 72);
            #pragma unroll
            for (int j = 0; j < 2; j++) {
                wmma::fragment<wmma::matrix_b, 16, 16, 16, __half, wmma::row_major> b;
                wmma::load_matrix_sync(b, sB + (kk * 16) * 72 + warpCol * 32 + j * 16, 72);
                wmma::mma_sync(acc[j], a, b, acc[j]);
            }
        }
    }

    #pragma unroll
    for (int j = 0; j < 2; j++)
        wmma::store_matrix_sync(
            gO + (size_t)(warpRow * 16) * SD_ + q * DK_ + warpCol * 32 + j * 16,
            acc[j], SD_, wmma::mem_row_major);
}

// ---------------------------------------------------------------------------
// Kernel 5: out = concat_heads(gO) @ Wp + bp. 3xbf16 split, tile 128x128.
// ---------------------------------------------------------------------------
__global__ __launch_bounds__(256, 2)
void final_kernel(const float* __restrict__ Wp, const float* __restrict__ bp,
                  float* __restrict__ out)
{
    __shared__ float sBias[16 * 136];
    __shared__ __nv_bfloat16 sAhi[128 * 40], sAlo[128 * 40];
    __shared__ __nv_bfloat16 sBhi[32 * 136], sBlo[32 * 136];

    const int tid = threadIdx.x;
    const int wid = tid >> 5;
    const int warpRow = wid >> 1;   // 0..3 -> 32 rows
    const int warpCol = wid & 1;    // 0..1 -> 64 cols
    const int m0 = blockIdx.y * 128;
    const int n0 = blockIdx.x * 128;
    const int bb = m0 >> 10;
    const int sBase = m0 & 1023;

    #pragma unroll
    for (int i = 0; i < 8; i++) {
        int idx = tid + i * 256;
        int r = idx >> 7, c = idx & 127;
        sBias[r * 136 + c] = bp[n0 + c];
    }
    __syncthreads();

    wmma::fragment<wmma::accumulator, 16, 16, 16, float> acc[2][4];
    #pragma unroll
    for (int mi = 0; mi < 2; mi++)
        #pragma unroll
        for (int ni = 0; ni < 4; ni++)
            wmma::load_matrix_sync(acc[mi][ni], sBias + warpCol * 64 + ni * 16,
                                   136, wmma::mem_row_major);

    for (int kt = 0; kt < 16; kt++) {
        const int k0 = kt * 32;
        const int h = k0 >> 6, d0 = k0 & 63;
        const float* Abase = gO + ((size_t)((bb * H_ + h) << 16)) + d0;
        #pragma unroll
        for (int i = 0; i < 4; i++) {
            int fi = tid + i * 256;
            int row = fi >> 3, c4 = (fi & 7) * 4;
            float4 v = *(const float4*)(Abase + (size_t)(sBase + row) * DK_ + c4);
            __nv_bfloat16 hx = __float2bfloat16(v.x), hy = __float2bfloat16(v.y);
            __nv_bfloat16 hz = __float2bfloat16(v.z), hw = __float2bfloat16(v.w);
            *(__nv_bfloat162*)&sAhi[row * 40 + c4]     = __nv_bfloat162(hx, hy);
            *(__nv_bfloat162*)&sAhi[row * 40 + c4 + 2] = __nv_bfloat162(hz, hw);
            *(__nv_bfloat162*)&sAlo[row * 40 + c4] =
                __nv_bfloat162(__float2bfloat16(v.x - __bfloat162float(hx)),
                               __float2bfloat16(v.y - __bfloat162float(hy)));
            *(__nv_bfloat162*)&sAlo[row * 40 + c4 + 2] =
                __nv_bfloat162(__float2bfloat16(v.z - __bfloat162float(hz)),
                               __float2bfloat16(v.w - __bfloat162float(hw)));
        }
        #pragma unroll
        for (int i = 0; i < 4; i++) {
            int fi = tid + i * 256;
            int row = fi >> 5, c4 = (fi & 31) * 4;
            float4 v = *(const float4*)(Wp + (k0 + row) * HD_ + n0 + c4);
            __nv_bfloat16 hx = __float2bfloat16(v.x), hy = __float2bfloat16(v.y);
            __nv_bfloat16 hz = __float2bfloat16(v.z), hw = __float2bfloat16(v.w);
            *(__nv_bfloat162*)&sBhi[row * 136 + c4]     = __nv_bfloat162(hx, hy);
            *(__nv_bfloat162*)&sBhi[row * 136 + c4 + 2] = __nv_bfloat162(hz, hw);
            *(__nv_bfloat162*)&sBlo[row * 136 + c4] =
                __nv_bfloat162(__float2bfloat16(v.x - __bfloat162float(hx)),
                               __float2bfloat16(v.y - __bfloat162float(hy)));
            *(__nv_bfloat162*)&sBlo[row * 136 + c4 + 2] =
                __nv_bfloat162(__float2bfloat16(v.z - __bfloat162float(hz)),
                               __float2bfloat16(v.w - __bfloat162float(hw)));
        }
        __syncthreads();
        #pragma unroll
        for (int kk = 0; kk < 2; kk++) {
            #pragma unroll
            for (int mi = 0; mi < 2; mi++) {
                wmma::fragment<wmma::matrix_a, 16, 16, 16, __nv_bfloat16, wmma::row_major> ah, al;
                wmma::load_matrix_sync(ah, sAhi + (warpRow * 32 + mi * 16) * 40 + kk * 16, 40);
                wmma::load_matrix_sync(al, sAlo + (warpRow * 32 + mi * 16) * 40 + kk * 16, 40);
                #pragma unroll
                for (int ni = 0; ni < 4; ni++) {
                    wmma::fragment<wmma::matrix_b, 16, 16, 16, __nv_bfloat16, wmma::row_major> bh, bl;
                    wmma::load_matrix_sync(bh, sBhi + (kk * 16) * 136 + warpCol * 64 + ni * 16, 136);
                    wmma::load_matrix_sync(bl, sBlo + (kk * 16) * 136 + warpCol * 64 + ni * 16, 136);
                    wmma::mma_sync(acc[mi][ni], ah, bh, acc[mi][ni]);
                    wmma::mma_sync(acc[mi][ni], ah, bl, acc[mi][ni]);
                    wmma::mma_sync(acc[mi][ni], al, bh, acc[mi][ni]);
                }
            }
        }
        __syncthreads();
    }

    #pragma unroll
    for (int mi = 0; mi < 2; mi++)
        #pragma unroll
        for (int ni = 0; ni < 4; ni++)
            wmma::store_matrix_sync(
                out + (size_t)(m0 + warpRow * 32 + mi * 16) * HD_ + n0 + warpCol * 64 + ni * 16,
                acc[mi][ni], HD_, wmma::mem_row_major);
}

// ---------------------------------------------------------------------------
extern "C" void kernel_launch(void* const* d_in, const int* in_sizes, int n_in,
                              void* d_out, int out_size)
{
    const float* queries = (const float*)d_in[0];
    const float* keys    = (const float*)d_in[1];
    const float* values  = (const float*)d_in[2];
    const float* Ek      = (const float*)d_in[3];
    const float* Ev      = (const float*)d_in[4];
    const float* abias   = (const float*)d_in[5];
    const float* Wq = (const float*)d_in[6];
    const float* bq = (const float*)d_in[7];
    const float* Wk = (const float*)d_in[8];
    const float* bk = (const float*)d_in[9];
    const float* Wv = (const float*)d_in[10];
    const float* bv = (const float*)d_in[11];
    const float* Wp = (const float*)d_in[12];
    const float* bp = (const float*)d_in[13];
    float* out = (float*)d_out;

    const int SMEM_PR = 128 * 68 * 4;                                   // 34816
    const int SMEM_EB = 2 * 64 * 72 * 2 + 64 * 72 * 4;                  // 36864
    const int SMEM_FA = (16 * 72 + 128 * 72) * 2 + 16 * THP * 2;        // 53760
    cudaFuncSetAttribute(fused_attn_kernel, cudaFuncAttributeMaxDynamicSharedMemorySize, SMEM_FA);

    dim3 blk(256);
    proj_kernel<<<dim3(8, 64, 3), blk, SMEM_PR>>>(queries, keys, values, Wq, Wk, Wv, bq, bk, bv);
    edge_bias_kernel<<<dim3(16, 1024), blk, SMEM_EB>>>(Ek, abias);
    fused_attn_kernel<<<dim3(64, 64), blk, SMEM_FA>>>();
    edgev_kernel<<<1024, blk>>>(Ev);
    final_kernel<<<dim3(4, 64), blk>>>(Wp, bp, out);
}